// round 12
// baseline (speedup 1.0000x reference)
#include <cuda_runtime.h>
#include <math.h>
#include <stdint.h>

#define N_IN  32768
#define KC    4096
#define DIM   256
#define M_TILE 128
#define NT_COLS 64
#define N_NT   (KC / NT_COLS)            // 64 N-tiles; full K per tile
#define STAGES 3
#define STG_BYTES (NT_COLS * DIM)        // 16KB per B stage (64 cols x 256 fp8)
#define A_BYTES  (M_TILE * DIM)          // 32KB resident A (2 chunks of 16KB)
#define EPS 3e-3f
#define DEQ2 4.8828125e-04f              // 2 * 2^-12 (w prescaled by 2^12)

// ---- scratch (device globals; no allocation allowed) ----
__device__ uint8_t g_Xf8[(size_t)N_IN * DIM];   // 8MB  e4m3(x)
__device__ uint8_t g_Wf8[(size_t)KC   * DIM];   // 1MB  e4m3(w * 4096)
__device__ float  g_A[N_IN];
__device__ float  g_B[KC];
__device__ int    g_argmin[N_IN];
__device__ int    g_counts[KC];
__device__ double g_partial[512];

// ===========================================================================
// helpers
// ===========================================================================
__device__ __forceinline__ uint32_t smem_u32(const void* p) {
    uint32_t a;
    asm("{ .reg .u64 t; cvta.to.shared.u64 t, %1; cvt.u32.u64 %0, t; }" : "=r"(a) : "l"(p));
    return a;
}
#define CP_ASYNC16(dst, src) \
    asm volatile("cp.async.cg.shared.global [%0], [%1], 16;" :: "r"(dst), "l"(src) : "memory")
#define CP_COMMIT() asm volatile("cp.async.commit_group;" ::: "memory")

__device__ __forceinline__ uint32_t swz(uint32_t off) { return off ^ ((off >> 3) & 0x70); }

__device__ __forceinline__ void ldsm4(uint32_t* r, uint32_t addr) {
    asm volatile("ldmatrix.sync.aligned.m8n8.x4.shared.b16 {%0,%1,%2,%3}, [%4];"
        : "=r"(r[0]), "=r"(r[1]), "=r"(r[2]), "=r"(r[3]) : "r"(addr));
}
// e4m3 x e4m3 -> f32, m16n8k32
__device__ __forceinline__ void mma_fp8(float* c, const uint32_t* a, uint32_t b0, uint32_t b1) {
    asm volatile("mma.sync.aligned.m16n8k32.row.col.f32.e4m3.e4m3.f32 "
        "{%0,%1,%2,%3}, {%4,%5,%6,%7}, {%8,%9}, {%0,%1,%2,%3};"
        : "+f"(c[0]), "+f"(c[1]), "+f"(c[2]), "+f"(c[3])
        : "r"(a[0]), "r"(a[1]), "r"(a[2]), "r"(a[3]), "r"(b0), "r"(b1));
}
__device__ __forceinline__ bool lex_less(float v1, int i1, float v2, int i2) {
    return v1 < v2 || (v1 == v2 && i1 < i2);
}
__device__ __forceinline__ uint16_t cvt_e4m3x2(float hi, float lo) {
    uint16_t o;
    asm("cvt.rn.satfinite.e4m3x2.f32 %0, %1, %2;" : "=h"(o) : "f"(hi), "f"(lo));
    return o;
}

// ===========================================================================
// small kernels
// ===========================================================================
__global__ void init_kernel() {
    int t = blockIdx.x * blockDim.x + threadIdx.x;
    if (t < KC) g_counts[t] = 0;
}

// fused fp8 convert (with scale) + row norms (EXACT same reduction order)
__global__ void prep_kernel(const float* __restrict__ src, uint8_t* __restrict__ dst,
                            float* __restrict__ norms, int nrows, float scale) {
    int warp = (blockIdx.x * blockDim.x + threadIdx.x) >> 5;
    int lane = threadIdx.x & 31;
    if (warp >= nrows) return;
    const float* r = src + (size_t)warp * DIM;

    // norms: element order lane + i*32, sequential adds, shfl tree (unchanged)
    float s = 0.f;
    #pragma unroll
    for (int i = 0; i < DIM / 32; i++) {
        float v = r[lane + i * 32];
        s = __fadd_rn(s, __fmul_rn(v, v));
    }
    #pragma unroll
    for (int o = 16; o > 0; o >>= 1)
        s = __fadd_rn(s, __shfl_xor_sync(0xffffffffu, s, o));
    if (lane == 0) norms[warp] = s;

    // fp8 conversion: pair p = lane + i*32 covers elems 2p, 2p+1
    uint16_t* d16 = (uint16_t*)(dst + (size_t)warp * DIM);
    #pragma unroll
    for (int i = 0; i < DIM / 64; i++) {
        int p = lane + i * 32;
        float e0 = r[2 * p]     * scale;
        float e1 = r[2 * p + 1] * scale;
        d16[p] = cvt_e4m3x2(e1, e0);   // hi byte = elem 2p+1, lo byte = elem 2p
    }
}

// ===========================================================================
// fp8 mma.sync distance GEMM + top-3 shortlist + exact fp32 refine
// CTA: 256 threads, 8 warps (4m x 2n), warp tile 32x32, CTA tile 128 rows.
// A (32KB fp8) resident; B streamed as 64 whole N-tiles (16KB = full K=256).
// Race-free order: wait -> sync -> issue t+2 -> mma t. 80KB smem, 2 CTAs/SM.
// Fused zeroing of this CTA's 128 encoding rows.
// ===========================================================================
__global__ __launch_bounds__(256, 2)
void gemm_mma_kernel(const float* __restrict__ x, const float* __restrict__ w,
                     float* __restrict__ out_enc) {
    extern __shared__ char smem[];
    const uint32_t sbase = smem_u32(smem);
    const int tid  = threadIdx.x;
    const int wid  = tid >> 5;
    const int lane = tid & 31;
    const int warp_m = wid & 3;       // 32-row slab (0..3)
    const int warp_n = wid >> 2;      // 32-col slab (0..1)
    const int row0 = blockIdx.x * M_TILE;

    const uint32_t A_OFF = 0;                    // 32KB: 2 chunks of 16KB (k-halves)
    const uint32_t B_OFF = A_BYTES;              // 48KB: 3 stages of 16KB

    // enc slice for this CTA: rows [row0, row0+128)
    float* enc_slice = out_enc + (size_t)row0 * KC;
    float4* encz = (float4*)(enc_slice + 2);     // 16B-aligned (base is 8-mod-16)
    const int N_F4 = (M_TILE * KC - 4) / 4;      // 131071

    // ldmatrix per-lane geometry (8-bit k32 fragments)
    const int a_row_l = (((lane >> 3) & 1) << 3) + (lane & 7);
    const int a_seg   = (lane >> 4) << 4;
    const int b_n_l   = ((lane >> 4) << 3) + (lane & 7);
    const int b_seg   = ((lane >> 3) & 1) << 4;

    float acc[2][4][4];
    #pragma unroll
    for (int mi = 0; mi < 2; mi++)
        #pragma unroll
        for (int ni = 0; ni < 4; ni++)
            #pragma unroll
            for (int q = 0; q < 4; q++) acc[mi][ni][q] = 0.f;

    // top-3 per local row (4 local rows per thread), lex-sorted ascending.
    // approx metric omits the per-row A term (constant within a row).
    float cv[4][3];
    int   ci[4][3];
    #pragma unroll
    for (int lr = 0; lr < 4; lr++) {
        cv[lr][0] = cv[lr][1] = cv[lr][2] = 3.4e38f;
        ci[lr][0] = ci[lr][1] = ci[lr][2] = 0x7fffffff;
    }

    const uint8_t* xs = g_Xf8 + (size_t)row0 * DIM;

    // ---- load resident A (2 chunks x 16KB: rows x 128B k-halves) ----
    #pragma unroll
    for (int blk = 0; blk < 2; blk++) {
        const uint32_t Ab = sbase + A_OFF + blk * 16384;
        const uint8_t* ga = xs + blk * 128;
        #pragma unroll
        for (int i = 0; i < 4; i++) {
            int id = tid + i * 256;
            int r = id >> 3, k8 = id & 7;
            CP_ASYNC16(Ab + swz(r * 128 + k8 * 16), ga + (size_t)r * DIM + k8 * 16);
        }
    }
    CP_COMMIT();

    // ---- B tile issue: 64 cols x 256B as 2 sub-blocks (k-halves) of 8KB ----
    #define ISSUE_B(tt_) do {                                                 \
        const int s_ = (tt_) % 3;                                             \
        const uint32_t Bst_ = sbase + B_OFF + s_ * STG_BYTES;                 \
        const uint8_t* gb0_ = g_Wf8 + (size_t)((tt_) * NT_COLS) * DIM;        \
        _Pragma("unroll")                                                     \
        for (int sub = 0; sub < 2; sub++) {                                   \
            const uint32_t Bb_ = Bst_ + sub * 8192;                           \
            const uint8_t* gb_ = gb0_ + sub * 128;                            \
            _Pragma("unroll")                                                 \
            for (int i = 0; i < 2; i++) {                                     \
                int id = tid + i * 256;                                       \
                int r = id >> 3, k8 = id & 7;                                 \
                CP_ASYNC16(Bb_ + swz(r * 128 + k8 * 16), gb_ + (size_t)r * DIM + k8 * 16); \
            }                                                                 \
        }                                                                     \
        CP_COMMIT();                                                          \
    } while (0)

    ISSUE_B(0);
    ISSUE_B(1);

    #pragma unroll 1
    for (int t = 0; t < N_NT; t++) {
        if (t + 1 < N_NT) asm volatile("cp.async.wait_group 1;" ::: "memory");
        else              asm volatile("cp.async.wait_group 0;" ::: "memory");
        __syncthreads();
        if (t + 2 < N_NT) ISSUE_B(t + 2);

        // fused enc zeroing: 8 coalesced float4 stores per thread per tile
        {
            const float4 z4 = make_float4(0.f, 0.f, 0.f, 0.f);
            const int base = t * 2048 + tid;
            #pragma unroll
            for (int j = 0; j < 8; j++) {
                int idx = base + j * 256;
                if (idx < N_F4) encz[idx] = z4;
            }
            if (t == 0 && tid == 0) {
                enc_slice[0] = 0.f; enc_slice[1] = 0.f;
                enc_slice[(size_t)M_TILE * KC - 2] = 0.f;
                enc_slice[(size_t)M_TILE * KC - 1] = 0.f;
            }
        }

        const uint32_t Bst = sbase + B_OFF + (t % 3) * STG_BYTES;

        // full K = 8 steps of k32
        #pragma unroll
        for (int step = 0; step < 8; step++) {
            const uint32_t Ab = sbase + A_OFF + (step >> 2) * 16384;
            const uint32_t Bb = Bst + (step >> 2) * 8192;
            const int kb = (step & 3) * 32;
            uint32_t af[2][4];
            #pragma unroll
            for (int mi = 0; mi < 2; mi++)
                ldsm4(af[mi], Ab + swz((warp_m * 32 + mi * 16 + a_row_l) * 128
                                       + kb + a_seg));
            uint32_t bf[2][4];
            #pragma unroll
            for (int pp = 0; pp < 2; pp++)
                ldsm4(bf[pp], Bb + swz((warp_n * 32 + pp * 16 + b_n_l) * 128
                                       + kb + b_seg));
            #pragma unroll
            for (int mi = 0; mi < 2; mi++)
                #pragma unroll
                for (int ni = 0; ni < 4; ni++)
                    mma_fp8(acc[mi][ni], af[mi],
                            bf[ni >> 1][(ni & 1) * 2], bf[ni >> 1][(ni & 1) * 2 + 1]);
        }

        // N-tile finished: approx v' = B[col] - acc*2^-11, maintain top-3
        {
            const int colbase = t * NT_COLS + warp_n * 32;
            #pragma unroll
            for (int mi = 0; mi < 2; mi++)
                #pragma unroll
                for (int h = 0; h < 2; h++) {
                    const int lr = mi * 2 + h;
                    #pragma unroll
                    for (int ni = 0; ni < 4; ni++)
                        #pragma unroll
                        for (int cc = 0; cc < 2; cc++) {
                            const int col = colbase + ni * 8 + 2 * (lane & 3) + cc;
                            float d = acc[mi][ni][h * 2 + cc];
                            float v = __fsub_rn(g_B[col], d * DEQ2);
                            if (lex_less(v, col, cv[lr][2], ci[lr][2])) {
                                if (lex_less(v, col, cv[lr][1], ci[lr][1])) {
                                    cv[lr][2] = cv[lr][1]; ci[lr][2] = ci[lr][1];
                                    if (lex_less(v, col, cv[lr][0], ci[lr][0])) {
                                        cv[lr][1] = cv[lr][0]; ci[lr][1] = ci[lr][0];
                                        cv[lr][0] = v;         ci[lr][0] = col;
                                    } else {
                                        cv[lr][1] = v;         ci[lr][1] = col;
                                    }
                                } else {
                                    cv[lr][2] = v;             ci[lr][2] = col;
                                }
                            }
                            acc[mi][ni][h * 2 + cc] = 0.f;
                        }
                }
        }
    }

    // gather shortlist to smem (reuse A region): 128 rows x 24 entries
    __syncthreads();
    float* redv = (float*)smem;                    // 12KB
    int*   redi = (int*)(smem + 128 * 24 * 4);     // 12KB
    #pragma unroll
    for (int lr = 0; lr < 4; lr++) {
        int mi = lr >> 1, h = lr & 1;
        const int row = warp_m * 32 + mi * 16 + h * 8 + (lane >> 2);
        const int slot = (warp_n * 4 + (lane & 3)) * 3;
        #pragma unroll
        for (int j = 0; j < 3; j++) {
            redv[row * 24 + slot + j] = cv[lr][j];
            redi[row * 24 + slot + j] = ci[lr][j];
        }
    }
    __syncthreads();

    // exact fp32 refine: one thread per row (sequential fmaf order = R1-proven)
    if (tid < M_TILE) {
        const int row = row0 + tid;
        float gmin = 3.4e38f;
        #pragma unroll
        for (int j = 0; j < 24; j++)
            gmin = fminf(gmin, redv[tid * 24 + j]);
        const float thresh = gmin + EPS;
        const float Ar = g_A[row];
        const float* xr = x + (size_t)row * DIM;

        float bestv = 3.4e38f;
        int   besti = 0x7fffffff;
        for (int j = 0; j < 24; j++) {
            float va = redv[tid * 24 + j];
            int   col = redi[tid * 24 + j];
            if (va > thresh || col == 0x7fffffff) continue;
            const float* wr = w + (size_t)col * DIM;
            float dot = 0.f;
            #pragma unroll 8
            for (int k = 0; k < DIM; k++)
                dot = fmaf(xr[k], __ldg(wr + k), dot);
            float u = __fadd_rn(Ar, g_B[col]);
            float ve = __fsub_rn(u, __fmul_rn(2.0f, dot));
            if (lex_less(ve, col, bestv, besti)) { bestv = ve; besti = col; }
        }
        g_argmin[row] = besti;
    }
}

// ===========================================================================
// epilogue + finalize
// ===========================================================================
__global__ __launch_bounds__(256)
void epilogue_kernel(const float* __restrict__ x, const float* __restrict__ w,
                     float* __restrict__ out_qst, float* __restrict__ out_enc) {
    __shared__ double sred[256];
    const int tid = threadIdx.x;
    const int rowLocal = tid >> 2;
    const int sub = tid & 3;
    const int row = blockIdx.x * 64 + rowLocal;
    const int idx = g_argmin[row];

    const float* wr = w + (size_t)idx * DIM;
    const float* xr = x + (size_t)row * DIM;
    float* qr = out_qst + (size_t)row * DIM;

    double ls = 0.0;
    #pragma unroll 8
    for (int u = 0; u < DIM / 4; u++) {
        int e = u * 4 + sub;
        float wv = wr[e];
        float xv = xr[e];
        float dlt = __fsub_rn(wv, xv);
        qr[e] = __fadd_rn(xv, dlt);
        float t = __fmul_rn(dlt, dlt);
        ls += (double)t;
    }
    if (sub == 0) {
        out_enc[(size_t)row * KC + idx] = 1.0f;
        atomicAdd(&g_counts[idx], 1);
    }
    sred[tid] = ls;
    __syncthreads();
    #pragma unroll
    for (int s = 128; s > 0; s >>= 1) {
        if (tid < s) sred[tid] += sred[tid + s];
        __syncthreads();
    }
    if (tid == 0) g_partial[blockIdx.x] = sred[0];
}

__global__ __launch_bounds__(256)
void finalize_kernel(float* __restrict__ out_loss, float* __restrict__ out_perp) {
    __shared__ double sred[256];
    const int tid = threadIdx.x;

    double s = g_partial[tid] + g_partial[tid + 256];
    sred[tid] = s;
    __syncthreads();
    #pragma unroll
    for (int st = 128; st > 0; st >>= 1) {
        if (tid < st) sred[tid] += sred[tid + st];
        __syncthreads();
    }
    if (tid == 0) {
        double total = sred[0];
        float m = (float)(total / (double)((long long)N_IN * DIM));
        *out_loss = __fadd_rn(m, __fmul_rn(0.25f, m));
    }
    __syncthreads();

    double ps = 0.0;
    #pragma unroll
    for (int i = 0; i < KC / 256; i++) {
        int k = tid + i * 256;
        float p = (float)g_counts[k] * (1.0f / (float)N_IN);
        float term = p * logf(__fadd_rn(p, 1e-10f));
        ps += (double)term;
    }
    sred[tid] = ps;
    __syncthreads();
    #pragma unroll
    for (int st = 128; st > 0; st >>= 1) {
        if (tid < st) sred[tid] += sred[tid + st];
        __syncthreads();
    }
    if (tid == 0) *out_perp = expf((float)(-sred[0]));
}

// ===========================================================================
extern "C" void kernel_launch(void* const* d_in, const int* in_sizes, int n_in,
                              void* d_out, int out_size) {
    const float* x = (const float*)d_in[0];
    const float* w = (const float*)d_in[1];
    if (n_in >= 2 && in_sizes[0] == KC * DIM && in_sizes[1] == N_IN * DIM) {
        x = (const float*)d_in[1];
        w = (const float*)d_in[0];
    }

    float* out = (float*)d_out;
    float* out_loss = out;
    float* out_qst  = out + 1;
    float* out_perp = out + 1 + (size_t)N_IN * DIM;
    float* out_enc  = out + 2 + (size_t)N_IN * DIM;

    uint8_t* xf8 = nullptr; uint8_t* wf8 = nullptr;
    float* ga = nullptr; float* gb = nullptr;
    cudaGetSymbolAddress((void**)&xf8, g_Xf8);
    cudaGetSymbolAddress((void**)&wf8, g_Wf8);
    cudaGetSymbolAddress((void**)&ga, g_A);
    cudaGetSymbolAddress((void**)&gb, g_B);

    const int SMEM_BYTES = A_BYTES + STAGES * STG_BYTES;   // 80KB
    cudaFuncSetAttribute(gemm_mma_kernel, cudaFuncAttributeMaxDynamicSharedMemorySize, SMEM_BYTES);

    init_kernel<<<(KC + 255) / 256, 256>>>();
    prep_kernel<<<N_IN / 8, 256>>>(x, xf8, ga, N_IN, 1.0f);
    prep_kernel<<<KC / 8, 256>>>(w, wf8, gb, KC, 4096.0f);

    gemm_mma_kernel<<<N_IN / M_TILE, 256, SMEM_BYTES>>>(x, w, out_enc);

    epilogue_kernel<<<N_IN / 64, 256>>>(x, w, out_qst, out_enc);
    finalize_kernel<<<1, 256>>>(out_loss, out_perp);
}

// round 13
// speedup vs baseline: 1.2587x; 1.2587x over previous
#include <cuda_runtime.h>
#include <cuda_bf16.h>
#include <math.h>
#include <stdint.h>

#define N_IN  32768
#define KC    4096
#define DIM   256
#define M_TILE 64
#define NT_COLS 64
#define K_CH   64                        // bf16 elems per chunk = 128B per row
#define N_NT   (KC / NT_COLS)            // 64
#define CH_PER_NT (DIM / K_CH)           // 4
#define N_CHUNKS (N_NT * CH_PER_NT)      // 256 B-chunks
#define STAGES 3
#define STG_BYTES (NT_COLS * 128)        // 8KB per B stage
#define A_BYTES  (M_TILE * DIM * 2)      // 32KB resident A (4 blocks of 8KB)
#define EPS 5e-4f

// ---- scratch (device globals; no allocation allowed) ----
__device__ __nv_bfloat16 g_Xbf[(size_t)N_IN * DIM];   // 16MB
__device__ __nv_bfloat16 g_Wbf[(size_t)KC   * DIM];   // 2MB
__device__ float  g_A[N_IN];
__device__ float  g_B[KC];
__device__ int    g_argmin[N_IN];
__device__ int    g_counts[KC];
__device__ double g_partial[512];

// ===========================================================================
// helpers
// ===========================================================================
__device__ __forceinline__ uint32_t smem_u32(const void* p) {
    uint32_t a;
    asm("{ .reg .u64 t; cvta.to.shared.u64 t, %1; cvt.u32.u64 %0, t; }" : "=r"(a) : "l"(p));
    return a;
}
#define CP_ASYNC16(dst, src) \
    asm volatile("cp.async.cg.shared.global [%0], [%1], 16;" :: "r"(dst), "l"(src) : "memory")
#define CP_COMMIT() asm volatile("cp.async.commit_group;" ::: "memory")

__device__ __forceinline__ uint32_t swz(uint32_t off) { return off ^ ((off >> 3) & 0x70); }

__device__ __forceinline__ void ldsm4(uint32_t* r, uint32_t addr) {
    asm volatile("ldmatrix.sync.aligned.m8n8.x4.shared.b16 {%0,%1,%2,%3}, [%4];"
        : "=r"(r[0]), "=r"(r[1]), "=r"(r[2]), "=r"(r[3]) : "r"(addr));
}
__device__ __forceinline__ void mma_bf16(float* c, const uint32_t* a, uint32_t b0, uint32_t b1) {
    asm volatile("mma.sync.aligned.m16n8k16.row.col.f32.bf16.bf16.f32 "
        "{%0,%1,%2,%3}, {%4,%5,%6,%7}, {%8,%9}, {%0,%1,%2,%3};"
        : "+f"(c[0]), "+f"(c[1]), "+f"(c[2]), "+f"(c[3])
        : "r"(a[0]), "r"(a[1]), "r"(a[2]), "r"(a[3]), "r"(b0), "r"(b1));
}
__device__ __forceinline__ bool lex_less(float v1, int i1, float v2, int i2) {
    return v1 < v2 || (v1 == v2 && i1 < i2);
}

// ===========================================================================
// small kernels
// ===========================================================================
__global__ void init_kernel() {
    int t = blockIdx.x * blockDim.x + threadIdx.x;
    if (t < KC) g_counts[t] = 0;
}

// fused bf16 convert + row norms (exact same reduction order as before)
__global__ void prep_kernel(const float* __restrict__ src, __nv_bfloat16* __restrict__ dst,
                            float* __restrict__ norms, int nrows) {
    int warp = (blockIdx.x * blockDim.x + threadIdx.x) >> 5;
    int lane = threadIdx.x & 31;
    if (warp >= nrows) return;
    const float* r = src + (size_t)warp * DIM;
    __nv_bfloat16* d = dst + (size_t)warp * DIM;
    float s = 0.f;
    #pragma unroll
    for (int i = 0; i < DIM / 32; i++) {
        float v = r[lane + i * 32];
        d[lane + i * 32] = __float2bfloat16(v);
        s = __fadd_rn(s, __fmul_rn(v, v));
    }
    #pragma unroll
    for (int o = 16; o > 0; o >>= 1)
        s = __fadd_rn(s, __shfl_xor_sync(0xffffffffu, s, o));
    if (lane == 0) norms[warp] = s;
}

// ===========================================================================
// bf16 mma.sync distance GEMM + top-2 shortlist + exact fp32 refine
// CTA: 256 threads, 8 warps (4m x 2n), warp tile 16x32, CTA tile 64 rows.
// A (32KB) resident; B streamed 3 x 8KB stages, race-free order.
// __launch_bounds__(256,3): regs <= ~84 -> 3 CTAs/SM = 24 warps (168KB smem).
// Approx metric drops per-row A term (ordering-invariant). Fused enc zeroing.
// ===========================================================================
__global__ __launch_bounds__(256, 3)
void gemm_mma_kernel(const float* __restrict__ x, const float* __restrict__ w,
                     float* __restrict__ out_enc) {
    extern __shared__ char smem[];
    const uint32_t sbase = smem_u32(smem);
    const int tid  = threadIdx.x;
    const int wid  = tid >> 5;
    const int lane = tid & 31;
    const int warp_m = wid & 3;       // 16-row slab (0..3)
    const int warp_n = wid >> 2;      // 32-col slab (0..1)
    const int row0 = blockIdx.x * M_TILE;

    const uint32_t A_OFF = 0;                    // 32KB: 4 blocks of 8KB (per k-chunk)
    const uint32_t B_OFF = A_BYTES;              // 24KB B stages

    // enc slice for this CTA: rows [row0, row0+64)
    float* enc_slice = out_enc + (size_t)row0 * KC;
    float4* encz = (float4*)(enc_slice + 2);     // 16B-aligned (base is 8-mod-16)
    const int N_F4 = (M_TILE * KC - 4) / 4;      // 65535

    // ldmatrix per-lane geometry (canonical x4 non-trans)
    const int a_row_l = (((lane >> 3) & 1) << 3) + (lane & 7);
    const int a_seg   = (lane >> 4) << 4;
    const int b_n_l   = ((lane >> 4) << 3) + (lane & 7);
    const int b_seg   = ((lane >> 3) & 1) << 4;

    float acc[4][4];                  // [ni][q]: one m16 row-slab x 4 n-octets
    #pragma unroll
    for (int ni = 0; ni < 4; ni++)
        #pragma unroll
        for (int q = 0; q < 4; q++) acc[ni][q] = 0.f;

    // top-2 per local row (2 local rows per thread: h=0,1), lex-sorted ascending
    float cv[2][2];
    int   ci[2][2];
    #pragma unroll
    for (int lr = 0; lr < 2; lr++) {
        cv[lr][0] = cv[lr][1] = 3.4e38f;
        ci[lr][0] = ci[lr][1] = 0x7fffffff;
    }

    const __nv_bfloat16* xs = g_Xbf + (size_t)row0 * DIM;

    // ---- load resident A (4 blocks x 8KB), one commit group ----
    #pragma unroll
    for (int blk = 0; blk < 4; blk++) {
        const uint32_t Ab = sbase + A_OFF + blk * 8192;
        const __nv_bfloat16* ga = xs + blk * K_CH;
        #pragma unroll
        for (int i = 0; i < 2; i++) {
            int id = tid + i * 256;
            int r = id >> 3, k8 = id & 7;
            CP_ASYNC16(Ab + swz(r * 128 + k8 * 16), ga + (size_t)r * DIM + k8 * 8);
        }
    }
    CP_COMMIT();

    // ---- B chunk issue (64 rows x 128B = 512 x 16B; 2 per thread) ----
    #define ISSUE_B(cc_) do {                                                 \
        const int s_  = (cc_) % 3;                                            \
        const int nt_ = (cc_) >> 2;                                           \
        const int kc_ = (cc_) & 3;                                            \
        const uint32_t Bb_ = sbase + B_OFF + s_ * STG_BYTES;                  \
        const __nv_bfloat16* gb_ = g_Wbf + (size_t)(nt_ * NT_COLS) * DIM + kc_ * K_CH; \
        _Pragma("unroll")                                                     \
        for (int i = 0; i < 2; i++) {                                         \
            int id = tid + i * 256;                                           \
            int r = id >> 3, k8 = id & 7;                                     \
            CP_ASYNC16(Bb_ + swz(r * 128 + k8 * 16), gb_ + (size_t)r * DIM + k8 * 8); \
        }                                                                     \
        CP_COMMIT();                                                          \
    } while (0)

    ISSUE_B(0);
    ISSUE_B(1);

    #pragma unroll 1
    for (int c = 0; c < N_CHUNKS; c++) {
        if (c + 1 < N_CHUNKS) asm volatile("cp.async.wait_group 1;" ::: "memory");
        else                  asm volatile("cp.async.wait_group 0;" ::: "memory");
        __syncthreads();
        if (c + 2 < N_CHUNKS) ISSUE_B(c + 2);

        // fused enc zeroing: 1 coalesced float4 store per thread per chunk
        {
            const int base = c * 256 + tid;
            if (base < N_F4) encz[base] = make_float4(0.f, 0.f, 0.f, 0.f);
            if (c == 0 && tid == 0) {
                enc_slice[0] = 0.f; enc_slice[1] = 0.f;
                enc_slice[(size_t)M_TILE * KC - 2] = 0.f;
                enc_slice[(size_t)M_TILE * KC - 1] = 0.f;
            }
        }

        const uint32_t Ab = sbase + A_OFF + (c & 3) * 8192;
        const uint32_t Bb = sbase + B_OFF + (c % 3) * STG_BYTES;

        #pragma unroll
        for (int k16 = 0; k16 < 4; k16++) {
            const int kb = k16 * 32;
            uint32_t af[4];
            ldsm4(af, Ab + swz((warp_m * 16 + a_row_l) * 128 + kb + a_seg));
            uint32_t bf[2][4];
            #pragma unroll
            for (int p = 0; p < 2; p++)
                ldsm4(bf[p], Bb + swz((warp_n * 32 + p * 16 + b_n_l) * 128
                                      + kb + b_seg));
            #pragma unroll
            for (int ni = 0; ni < 4; ni++)
                mma_bf16(acc[ni], af,
                         bf[ni >> 1][(ni & 1) * 2], bf[ni >> 1][(ni & 1) * 2 + 1]);
        }

        if ((c & 3) == 3) {
            // N-tile finished: approx v = B[col] - 2*d (A-term dropped), top-2
            const int nt = c >> 2;
            const int colbase = nt * NT_COLS + warp_n * 32;
            #pragma unroll
            for (int h = 0; h < 2; h++) {
                #pragma unroll
                for (int ni = 0; ni < 4; ni++)
                    #pragma unroll
                    for (int cc = 0; cc < 2; cc++) {
                        const int col = colbase + ni * 8 + 2 * (lane & 3) + cc;
                        float d = acc[ni][h * 2 + cc];
                        float v = __fsub_rn(g_B[col], __fmul_rn(2.0f, d));
                        if (lex_less(v, col, cv[h][1], ci[h][1])) {
                            if (lex_less(v, col, cv[h][0], ci[h][0])) {
                                cv[h][1] = cv[h][0]; ci[h][1] = ci[h][0];
                                cv[h][0] = v;        ci[h][0] = col;
                            } else {
                                cv[h][1] = v;        ci[h][1] = col;
                            }
                        }
                        acc[ni][h * 2 + cc] = 0.f;
                    }
            }
        }
    }

    // gather shortlist to smem (reuse A region): 64 rows x 16 entries
    __syncthreads();
    float* redv = (float*)smem;                   // 4KB
    int*   redi = (int*)(smem + 64 * 16 * 4);     // 4KB
    #pragma unroll
    for (int h = 0; h < 2; h++) {
        const int row = warp_m * 16 + h * 8 + (lane >> 2);
        const int slot = (warp_n * 4 + (lane & 3)) * 2;
        #pragma unroll
        for (int j = 0; j < 2; j++) {
            redv[row * 16 + slot + j] = cv[h][j];
            redi[row * 16 + slot + j] = ci[h][j];
        }
    }
    __syncthreads();

    // exact fp32 refine: one thread per row (sequential fmaf order = R1-proven)
    if (tid < M_TILE) {
        const int row = row0 + tid;
        float gmin = 3.4e38f;
        #pragma unroll
        for (int j = 0; j < 16; j++)
            gmin = fminf(gmin, redv[tid * 16 + j]);
        const float thresh = gmin + EPS;
        const float Ar = g_A[row];
        const float* xr = x + (size_t)row * DIM;

        float bestv = 3.4e38f;
        int   besti = 0x7fffffff;
        for (int j = 0; j < 16; j++) {
            float va = redv[tid * 16 + j];
            int   col = redi[tid * 16 + j];
            if (va > thresh || col == 0x7fffffff) continue;
            const float* wr = w + (size_t)col * DIM;
            float dot = 0.f;
            #pragma unroll 8
            for (int k = 0; k < DIM; k++)
                dot = fmaf(xr[k], __ldg(wr + k), dot);
            float u = __fadd_rn(Ar, g_B[col]);
            float ve = __fsub_rn(u, __fmul_rn(2.0f, dot));
            if (lex_less(ve, col, bestv, besti)) { bestv = ve; besti = col; }
        }
        g_argmin[row] = besti;
    }
}

// ===========================================================================
// epilogue + finalize
// ===========================================================================
__global__ __launch_bounds__(256)
void epilogue_kernel(const float* __restrict__ x, const float* __restrict__ w,
                     float* __restrict__ out_qst, float* __restrict__ out_enc) {
    __shared__ double sred[256];
    const int tid = threadIdx.x;
    const int rowLocal = tid >> 2;
    const int sub = tid & 3;
    const int row = blockIdx.x * 64 + rowLocal;
    const int idx = g_argmin[row];

    const float* wr = w + (size_t)idx * DIM;
    const float* xr = x + (size_t)row * DIM;
    float* qr = out_qst + (size_t)row * DIM;

    double ls = 0.0;
    #pragma unroll 8
    for (int u = 0; u < DIM / 4; u++) {
        int e = u * 4 + sub;
        float wv = wr[e];
        float xv = xr[e];
        float dlt = __fsub_rn(wv, xv);
        qr[e] = __fadd_rn(xv, dlt);
        float t = __fmul_rn(dlt, dlt);
        ls += (double)t;
    }
    if (sub == 0) {
        out_enc[(size_t)row * KC + idx] = 1.0f;
        atomicAdd(&g_counts[idx], 1);
    }
    sred[tid] = ls;
    __syncthreads();
    #pragma unroll
    for (int s = 128; s > 0; s >>= 1) {
        if (tid < s) sred[tid] += sred[tid + s];
        __syncthreads();
    }
    if (tid == 0) g_partial[blockIdx.x] = sred[0];
}

__global__ __launch_bounds__(256)
void finalize_kernel(float* __restrict__ out_loss, float* __restrict__ out_perp) {
    __shared__ double sred[256];
    const int tid = threadIdx.x;

    double s = g_partial[tid] + g_partial[tid + 256];
    sred[tid] = s;
    __syncthreads();
    #pragma unroll
    for (int st = 128; st > 0; st >>= 1) {
        if (tid < st) sred[tid] += sred[tid + st];
        __syncthreads();
    }
    if (tid == 0) {
        double total = sred[0];
        float m = (float)(total / (double)((long long)N_IN * DIM));
        *out_loss = __fadd_rn(m, __fmul_rn(0.25f, m));
    }
    __syncthreads();

    double ps = 0.0;
    #pragma unroll
    for (int i = 0; i < KC / 256; i++) {
        int k = tid + i * 256;
        float p = (float)g_counts[k] * (1.0f / (float)N_IN);
        float term = p * logf(__fadd_rn(p, 1e-10f));
        ps += (double)term;
    }
    sred[tid] = ps;
    __syncthreads();
    #pragma unroll
    for (int st = 128; st > 0; st >>= 1) {
        if (tid < st) sred[tid] += sred[tid + st];
        __syncthreads();
    }
    if (tid == 0) *out_perp = expf((float)(-sred[0]));
}

// ===========================================================================
extern "C" void kernel_launch(void* const* d_in, const int* in_sizes, int n_in,
                              void* d_out, int out_size) {
    const float* x = (const float*)d_in[0];
    const float* w = (const float*)d_in[1];
    if (n_in >= 2 && in_sizes[0] == KC * DIM && in_sizes[1] == N_IN * DIM) {
        x = (const float*)d_in[1];
        w = (const float*)d_in[0];
    }

    float* out = (float*)d_out;
    float* out_loss = out;
    float* out_qst  = out + 1;
    float* out_perp = out + 1 + (size_t)N_IN * DIM;
    float* out_enc  = out + 2 + (size_t)N_IN * DIM;

    __nv_bfloat16* xbf = nullptr; __nv_bfloat16* wbf = nullptr;
    float* ga = nullptr; float* gb = nullptr;
    cudaGetSymbolAddress((void**)&xbf, g_Xbf);
    cudaGetSymbolAddress((void**)&wbf, g_Wbf);
    cudaGetSymbolAddress((void**)&ga, g_A);
    cudaGetSymbolAddress((void**)&gb, g_B);

    const int SMEM_BYTES = A_BYTES + STAGES * STG_BYTES;   // 56KB
    cudaFuncSetAttribute(gemm_mma_kernel, cudaFuncAttributeMaxDynamicSharedMemorySize, SMEM_BYTES);

    init_kernel<<<(KC + 255) / 256, 256>>>();
    prep_kernel<<<N_IN / 8, 256>>>(x, xbf, ga, N_IN);
    prep_kernel<<<KC / 8, 256>>>(w, wbf, gb, KC);

    gemm_mma_kernel<<<N_IN / M_TILE, 256, SMEM_BYTES>>>(x, w, out_enc);

    epilogue_kernel<<<N_IN / 64, 256>>>(x, w, out_qst, out_enc);
    finalize_kernel<<<1, 256>>>(out_loss, out_perp);
}

// round 15
// speedup vs baseline: 1.2910x; 1.0256x over previous
#include <cuda_runtime.h>
#include <cuda_fp16.h>
#include <math.h>
#include <stdint.h>

#define N_IN  32768
#define KC    4096
#define DIM   256
#define M_TILE 128
#define NT_COLS 128
#define K_CH   64                        // f16 elems per chunk = 128B per row
#define N_NT   (KC / NT_COLS)            // 32
#define CH_PER_NT (DIM / K_CH)           // 4
#define N_CHUNKS (N_NT * CH_PER_NT)      // 128 B-chunks
#define STAGES 3
#define STG_BYTES (NT_COLS * 128)        // 16KB per B stage (128 cols x 64 k)
#define A_BYTES  (M_TILE * DIM * 2)      // 64KB resident A (4 blocks of 16KB)
#define EPS 2e-3f

// ---- scratch (device globals; no allocation allowed) ----
__device__ __half g_Xh[(size_t)N_IN * DIM];   // 16MB
__device__ __half g_Wh[(size_t)KC   * DIM];   // 2MB
__device__ float  g_A[N_IN];
__device__ float  g_B[KC];
__device__ int    g_argmin[N_IN];
__device__ int    g_counts[KC];
__device__ double g_partial[512];

// ===========================================================================
// helpers
// ===========================================================================
__device__ __forceinline__ uint32_t smem_u32(const void* p) {
    uint32_t a;
    asm("{ .reg .u64 t; cvta.to.shared.u64 t, %1; cvt.u32.u64 %0, t; }" : "=r"(a) : "l"(p));
    return a;
}
#define CP_ASYNC16(dst, src) \
    asm volatile("cp.async.cg.shared.global [%0], [%1], 16;" :: "r"(dst), "l"(src) : "memory")
#define CP_COMMIT() asm volatile("cp.async.commit_group;" ::: "memory")

__device__ __forceinline__ uint32_t swz(uint32_t off) { return off ^ ((off >> 3) & 0x70); }

__device__ __forceinline__ void ldsm4(uint32_t* r, uint32_t addr) {
    asm volatile("ldmatrix.sync.aligned.m8n8.x4.shared.b16 {%0,%1,%2,%3}, [%4];"
        : "=r"(r[0]), "=r"(r[1]), "=r"(r[2]), "=r"(r[3]) : "r"(addr));
}
// f16 x f16 -> f16 acc, m16n8k16 (2 f16x2 C regs)
__device__ __forceinline__ void mma_f16(uint32_t* c, const uint32_t* a, uint32_t b0, uint32_t b1) {
    asm volatile("mma.sync.aligned.m16n8k16.row.col.f16.f16.f16.f16 "
        "{%0,%1}, {%2,%3,%4,%5}, {%6,%7}, {%0,%1};"
        : "+r"(c[0]), "+r"(c[1])
        : "r"(a[0]), "r"(a[1]), "r"(a[2]), "r"(a[3]), "r"(b0), "r"(b1));
}
__device__ __forceinline__ bool lex_less(float v1, int i1, float v2, int i2) {
    return v1 < v2 || (v1 == v2 && i1 < i2);
}

// ===========================================================================
// small kernels
// ===========================================================================
__global__ void init_kernel() {
    int t = blockIdx.x * blockDim.x + threadIdx.x;
    if (t < KC) g_counts[t] = 0;
}

// fused f16 convert + row norms (exact same reduction order as before)
__global__ void prep_kernel(const float* __restrict__ src, __half* __restrict__ dst,
                            float* __restrict__ norms, int nrows) {
    int warp = (blockIdx.x * blockDim.x + threadIdx.x) >> 5;
    int lane = threadIdx.x & 31;
    if (warp >= nrows) return;
    const float* r = src + (size_t)warp * DIM;
    __half* d = dst + (size_t)warp * DIM;
    float s = 0.f;
    #pragma unroll
    for (int i = 0; i < DIM / 32; i++) {
        float v = r[lane + i * 32];
        d[lane + i * 32] = __float2half(v);
        s = __fadd_rn(s, __fmul_rn(v, v));
    }
    #pragma unroll
    for (int o = 16; o > 0; o >>= 1)
        s = __fadd_rn(s, __shfl_xor_sync(0xffffffffu, s, o));
    if (lane == 0) norms[warp] = s;
}

// ===========================================================================
// f16 mma.sync (f16 acc) distance GEMM + top-3 shortlist + exact fp32 refine
// CTA: 256 threads, 8 warps (4m x 2n), warp tile 32x64, CTA tile 128x128.
// A (64KB) resident; B streamed 3 x 16KB stages, race-free order
// (wait -> sync -> issue c+2 -> mma c). 112KB smem, 2 CTAs/SM = 16 warps.
// Approx metric drops per-row A term (ordering-invariant). Fused enc zeroing.
// ===========================================================================
__global__ __launch_bounds__(256, 2)
void gemm_mma_kernel(const float* __restrict__ x, const float* __restrict__ w,
                     float* __restrict__ out_enc) {
    extern __shared__ char smem[];
    const uint32_t sbase = smem_u32(smem);
    const int tid  = threadIdx.x;
    const int wid  = tid >> 5;
    const int lane = tid & 31;
    const int warp_m = wid & 3;       // 32-row slab (0..3)
    const int warp_n = wid >> 2;      // 64-col slab (0..1)
    const int row0 = blockIdx.x * M_TILE;

    const uint32_t A_OFF = 0;                    // 64KB: 4 blocks of 16KB (per k-chunk)
    const uint32_t B_OFF = A_BYTES;              // 48KB B stages

    // enc slice for this CTA: rows [row0, row0+128)
    float* enc_slice = out_enc + (size_t)row0 * KC;
    float4* encz = (float4*)(enc_slice + 2);     // 16B-aligned (base is 8-mod-16)
    const int N_F4 = (M_TILE * KC - 4) / 4;      // 131071

    // ldmatrix per-lane geometry (canonical x4 non-trans)
    const int a_row_l = (((lane >> 3) & 1) << 3) + (lane & 7);
    const int a_seg   = (lane >> 4) << 4;
    const int b_n_l   = ((lane >> 4) << 3) + (lane & 7);
    const int b_seg   = ((lane >> 3) & 1) << 4;

    uint32_t acc[2][8][2];            // f16x2 accumulators
    #pragma unroll
    for (int mi = 0; mi < 2; mi++)
        #pragma unroll
        for (int ni = 0; ni < 8; ni++) {
            acc[mi][ni][0] = 0u; acc[mi][ni][1] = 0u;
        }

    // top-3 per local row (4 local rows per thread: mi x h), lex-sorted
    float cv[4][3];
    int   ci[4][3];
    #pragma unroll
    for (int lr = 0; lr < 4; lr++) {
        cv[lr][0] = cv[lr][1] = cv[lr][2] = 3.4e38f;
        ci[lr][0] = ci[lr][1] = ci[lr][2] = 0x7fffffff;
    }

    const __half* xs = g_Xh + (size_t)row0 * DIM;

    // ---- load resident A (4 blocks x 16KB), one commit group ----
    #pragma unroll
    for (int blk = 0; blk < 4; blk++) {
        const uint32_t Ab = sbase + A_OFF + blk * 16384;
        const __half* ga = xs + blk * K_CH;
        #pragma unroll
        for (int i = 0; i < 4; i++) {
            int id = tid + i * 256;
            int r = id >> 3, k8 = id & 7;
            CP_ASYNC16(Ab + swz(r * 128 + k8 * 16), ga + (size_t)r * DIM + k8 * 8);
        }
    }
    CP_COMMIT();

    // ---- B chunk issue (128 rows x 128B = 1024 x 16B; 4 per thread) ----
    #define ISSUE_B(cc_) do {                                                 \
        const int s_  = (cc_) % 3;                                            \
        const int nt_ = (cc_) >> 2;                                           \
        const int kc_ = (cc_) & 3;                                            \
        const uint32_t Bb_ = sbase + B_OFF + s_ * STG_BYTES;                  \
        const __half* gb_ = g_Wh + (size_t)(nt_ * NT_COLS) * DIM + kc_ * K_CH; \
        _Pragma("unroll")                                                     \
        for (int i = 0; i < 4; i++) {                                         \
            int id = tid + i * 256;                                           \
            int r = id >> 3, k8 = id & 7;                                     \
            CP_ASYNC16(Bb_ + swz(r * 128 + k8 * 16), gb_ + (size_t)r * DIM + k8 * 8); \
        }                                                                     \
        CP_COMMIT();                                                          \
    } while (0)

    ISSUE_B(0);
    ISSUE_B(1);

    #pragma unroll 1
    for (int c = 0; c < N_CHUNKS; c++) {
        if (c + 1 < N_CHUNKS) asm volatile("cp.async.wait_group 1;" ::: "memory");
        else                  asm volatile("cp.async.wait_group 0;" ::: "memory");
        __syncthreads();
        if (c + 2 < N_CHUNKS) ISSUE_B(c + 2);

        // fused enc zeroing: 4 coalesced float4 stores per thread per chunk
        {
            const float4 z4 = make_float4(0.f, 0.f, 0.f, 0.f);
            const int base = c * 1024 + tid;
            #pragma unroll
            for (int j = 0; j < 4; j++) {
                int idx = base + j * 256;
                if (idx < N_F4) encz[idx] = z4;
            }
            if (c == 0 && tid == 0) {
                enc_slice[0] = 0.f; enc_slice[1] = 0.f;
                enc_slice[(size_t)M_TILE * KC - 2] = 0.f;
                enc_slice[(size_t)M_TILE * KC - 1] = 0.f;
            }
        }

        const uint32_t Ab = sbase + A_OFF + (c & 3) * 16384;
        const uint32_t Bb = sbase + B_OFF + (c % 3) * STG_BYTES;

        #pragma unroll
        for (int k16 = 0; k16 < 4; k16++) {
            const int kb = k16 * 32;
            uint32_t af[2][4];
            #pragma unroll
            for (int mi = 0; mi < 2; mi++)
                ldsm4(af[mi], Ab + swz((warp_m * 32 + mi * 16 + a_row_l) * 128
                                       + kb + a_seg));
            uint32_t bf[4][4];
            #pragma unroll
            for (int p = 0; p < 4; p++)
                ldsm4(bf[p], Bb + swz((warp_n * 64 + p * 16 + b_n_l) * 128
                                      + kb + b_seg));
            #pragma unroll
            for (int mi = 0; mi < 2; mi++)
                #pragma unroll
                for (int ni = 0; ni < 8; ni++)
                    mma_f16(acc[mi][ni], af[mi],
                            bf[ni >> 1][(ni & 1) * 2], bf[ni >> 1][(ni & 1) * 2 + 1]);
        }

        if ((c & 3) == 3) {
            // N-tile finished: approx v = B[col] - 2*d (A-term dropped), top-3
            const int nt = c >> 2;
            const int colbase = nt * NT_COLS + warp_n * 64;
            #pragma unroll
            for (int mi = 0; mi < 2; mi++)
                #pragma unroll
                for (int h = 0; h < 2; h++) {
                    const int lr = mi * 2 + h;
                    #pragma unroll
                    for (int ni = 0; ni < 8; ni++) {
                        __half2 hv = *(__half2*)&acc[mi][ni][h];
                        float2 f2 = __half22float2(hv);
                        #pragma unroll
                        for (int cc = 0; cc < 2; cc++) {
                            const int col = colbase + ni * 8 + 2 * (lane & 3) + cc;
                            float d = (cc == 0) ? f2.x : f2.y;
                            float v = __fsub_rn(g_B[col], __fmul_rn(2.0f, d));
                            if (lex_less(v, col, cv[lr][2], ci[lr][2])) {
                                if (lex_less(v, col, cv[lr][1], ci[lr][1])) {
                                    cv[lr][2] = cv[lr][1]; ci[lr][2] = ci[lr][1];
                                    if (lex_less(v, col, cv[lr][0], ci[lr][0])) {
                                        cv[lr][1] = cv[lr][0]; ci[lr][1] = ci[lr][0];
                                        cv[lr][0] = v;         ci[lr][0] = col;
                                    } else {
                                        cv[lr][1] = v;         ci[lr][1] = col;
                                    }
                                } else {
                                    cv[lr][2] = v;             ci[lr][2] = col;
                                }
                            }
                        }
                        acc[mi][ni][h] = 0u;
                    }
                }
        }
    }

    // gather shortlist to smem (reuse A region): 128 rows x 24 entries
    __syncthreads();
    float* redv = (float*)smem;                    // 12KB
    int*   redi = (int*)(smem + 128 * 24 * 4);     // 12KB
    #pragma unroll
    for (int lr = 0; lr < 4; lr++) {
        int mi = lr >> 1, h = lr & 1;
        const int row = warp_m * 32 + mi * 16 + h * 8 + (lane >> 2);
        const int slot = (warp_n * 4 + (lane & 3)) * 3;
        #pragma unroll
        for (int j = 0; j < 3; j++) {
            redv[row * 24 + slot + j] = cv[lr][j];
            redi[row * 24 + slot + j] = ci[lr][j];
        }
    }
    __syncthreads();

    // exact fp32 refine: one thread per row (sequential fmaf order = R1-proven)
    if (tid < M_TILE) {
        const int row = row0 + tid;
        float gmin = 3.4e38f;
        #pragma unroll
        for (int j = 0; j < 24; j++)
            gmin = fminf(gmin, redv[tid * 24 + j]);
        const float thresh = gmin + EPS;
        const float Ar = g_A[row];
        const float* xr = x + (size_t)row * DIM;

        float bestv = 3.4e38f;
        int   besti = 0x7fffffff;
        for (int j = 0; j < 24; j++) {
            float va = redv[tid * 24 + j];
            int   col = redi[tid * 24 + j];
            if (va > thresh || col == 0x7fffffff) continue;
            const float* wr = w + (size_t)col * DIM;
            float dot = 0.f;
            #pragma unroll 8
            for (int k = 0; k < DIM; k++)
                dot = fmaf(xr[k], __ldg(wr + k), dot);
            float u = __fadd_rn(Ar, g_B[col]);
            float ve = __fsub_rn(u, __fmul_rn(2.0f, dot));
            if (lex_less(ve, col, bestv, besti)) { bestv = ve; besti = col; }
        }
        g_argmin[row] = besti;
    }
}

// ===========================================================================
// epilogue + finalize
// ===========================================================================
__global__ __launch_bounds__(256)
void epilogue_kernel(const float* __restrict__ x, const float* __restrict__ w,
                     float* __restrict__ out_qst, float* __restrict__ out_enc) {
    __shared__ double sred[256];
    const int tid = threadIdx.x;
    const int rowLocal = tid >> 2;
    const int sub = tid & 3;
    const int row = blockIdx.x * 64 + rowLocal;
    const int idx = g_argmin[row];

    const float* wr = w + (size_t)idx * DIM;
    const float* xr = x + (size_t)row * DIM;
    float* qr = out_qst + (size_t)row * DIM;

    double ls = 0.0;
    #pragma unroll 8
    for (int u = 0; u < DIM / 4; u++) {
        int e = u * 4 + sub;
        float wv = wr[e];
        float xv = xr[e];
        float dlt = __fsub_rn(wv, xv);
        qr[e] = __fadd_rn(xv, dlt);
        float t = __fmul_rn(dlt, dlt);
        ls += (double)t;
    }
    if (sub == 0) {
        out_enc[(size_t)row * KC + idx] = 1.0f;
        atomicAdd(&g_counts[idx], 1);
    }
    sred[tid] = ls;
    __syncthreads();
    #pragma unroll
    for (int s = 128; s > 0; s >>= 1) {
        if (tid < s) sred[tid] += sred[tid + s];
        __syncthreads();
    }
    if (tid == 0) g_partial[blockIdx.x] = sred[0];
}

__global__ __launch_bounds__(256)
void finalize_kernel(float* __restrict__ out_loss, float* __restrict__ out_perp) {
    __shared__ double sred[256];
    const int tid = threadIdx.x;

    double s = g_partial[tid] + g_partial[tid + 256];
    sred[tid] = s;
    __syncthreads();
    #pragma unroll
    for (int st = 128; st > 0; st >>= 1) {
        if (tid < st) sred[tid] += sred[tid + st];
        __syncthreads();
    }
    if (tid == 0) {
        double total = sred[0];
        float m = (float)(total / (double)((long long)N_IN * DIM));
        *out_loss = __fadd_rn(m, __fmul_rn(0.25f, m));
    }
    __syncthreads();

    double ps = 0.0;
    #pragma unroll
    for (int i = 0; i < KC / 256; i++) {
        int k = tid + i * 256;
        float p = (float)g_counts[k] * (1.0f / (float)N_IN);
        float term = p * logf(__fadd_rn(p, 1e-10f));
        ps += (double)term;
    }
    sred[tid] = ps;
    __syncthreads();
    #pragma unroll
    for (int st = 128; st > 0; st >>= 1) {
        if (tid < st) sred[tid] += sred[tid + st];
        __syncthreads();
    }
    if (tid == 0) *out_perp = expf((float)(-sred[0]));
}

// ===========================================================================
extern "C" void kernel_launch(void* const* d_in, const int* in_sizes, int n_in,
                              void* d_out, int out_size) {
    const float* x = (const float*)d_in[0];
    const float* w = (const float*)d_in[1];
    if (n_in >= 2 && in_sizes[0] == KC * DIM && in_sizes[1] == N_IN * DIM) {
        x = (const float*)d_in[1];
        w = (const float*)d_in[0];
    }

    float* out = (float*)d_out;
    float* out_loss = out;
    float* out_qst  = out + 1;
    float* out_perp = out + 1 + (size_t)N_IN * DIM;
    float* out_enc  = out + 2 + (size_t)N_IN * DIM;

    __half* xh = nullptr; __half* wh = nullptr;
    float* ga = nullptr; float* gb = nullptr;
    cudaGetSymbolAddress((void**)&xh, g_Xh);
    cudaGetSymbolAddress((void**)&wh, g_Wh);
    cudaGetSymbolAddress((void**)&ga, g_A);
    cudaGetSymbolAddress((void**)&gb, g_B);

    const int SMEM_BYTES = A_BYTES + STAGES * STG_BYTES;   // 112KB
    cudaFuncSetAttribute(gemm_mma_kernel, cudaFuncAttributeMaxDynamicSharedMemorySize, SMEM_BYTES);

    init_kernel<<<(KC + 255) / 256, 256>>>();
    prep_kernel<<<N_IN / 8, 256>>>(x, xh, ga, N_IN);
    prep_kernel<<<KC / 8, 256>>>(w, wh, gb, KC);

    gemm_mma_kernel<<<N_IN / M_TILE, 256, SMEM_BYTES>>>(x, w, out_enc);

    epilogue_kernel<<<N_IN / 64, 256>>>(x, w, out_qst, out_enc);
    finalize_kernel<<<1, 256>>>(out_loss, out_perp);
}

// round 16
// speedup vs baseline: 1.8698x; 1.4484x over previous
#include <cuda_runtime.h>
#include <cuda_bf16.h>
#include <math.h>
#include <stdint.h>

#define N_IN  32768
#define KC    4096
#define DIM   256
#define M_TILE 128
#define NT_COLS 128
#define K_CH   64                        // bf16 elems per chunk = 128B per row
#define N_NT   (KC / NT_COLS)            // 32
#define CH_PER_NT (DIM / K_CH)           // 4
#define N_CHUNKS (N_NT * CH_PER_NT)      // 128 B-chunks
#define STAGES 3
#define STG_BYTES (NT_COLS * 128)        // 16KB per B stage (128 cols x 64 k)
#define A_BYTES  (M_TILE * DIM * 2)      // 64KB resident A (4 blocks of 16KB)
#define EPS 5e-4f

// ---- scratch (device globals; no allocation allowed) ----
__device__ __nv_bfloat16 g_Xbf[(size_t)N_IN * DIM];   // 16MB
__device__ __nv_bfloat16 g_Wbf[(size_t)KC   * DIM];   // 2MB
__device__ float  g_A[N_IN];
__device__ float  g_B[KC];
__device__ int    g_argmin[N_IN];
__device__ int    g_counts[KC];
__device__ double g_partial[512];

// ===========================================================================
// helpers
// ===========================================================================
__device__ __forceinline__ uint32_t smem_u32(const void* p) {
    uint32_t a;
    asm("{ .reg .u64 t; cvta.to.shared.u64 t, %1; cvt.u32.u64 %0, t; }" : "=r"(a) : "l"(p));
    return a;
}
#define CP_ASYNC16(dst, src) \
    asm volatile("cp.async.cg.shared.global [%0], [%1], 16;" :: "r"(dst), "l"(src) : "memory")
#define CP_COMMIT() asm volatile("cp.async.commit_group;" ::: "memory")

__device__ __forceinline__ uint32_t swz(uint32_t off) { return off ^ ((off >> 3) & 0x70); }

__device__ __forceinline__ void ldsm4(uint32_t* r, uint32_t addr) {
    asm volatile("ldmatrix.sync.aligned.m8n8.x4.shared.b16 {%0,%1,%2,%3}, [%4];"
        : "=r"(r[0]), "=r"(r[1]), "=r"(r[2]), "=r"(r[3]) : "r"(addr));
}
__device__ __forceinline__ void mma_bf16(float* c, const uint32_t* a, uint32_t b0, uint32_t b1) {
    asm volatile("mma.sync.aligned.m16n8k16.row.col.f32.bf16.bf16.f32 "
        "{%0,%1,%2,%3}, {%4,%5,%6,%7}, {%8,%9}, {%0,%1,%2,%3};"
        : "+f"(c[0]), "+f"(c[1]), "+f"(c[2]), "+f"(c[3])
        : "r"(a[0]), "r"(a[1]), "r"(a[2]), "r"(a[3]), "r"(b0), "r"(b1));
}
__device__ __forceinline__ bool lex_less(float v1, int i1, float v2, int i2) {
    return v1 < v2 || (v1 == v2 && i1 < i2);
}

// ===========================================================================
// small kernels
// ===========================================================================
__global__ void init_kernel() {
    int t = blockIdx.x * blockDim.x + threadIdx.x;
    if (t < KC) g_counts[t] = 0;
}

// fused bf16 convert + row norms (exact same reduction order as before)
__global__ void prep_kernel(const float* __restrict__ src, __nv_bfloat16* __restrict__ dst,
                            float* __restrict__ norms, int nrows) {
    int warp = (blockIdx.x * blockDim.x + threadIdx.x) >> 5;
    int lane = threadIdx.x & 31;
    if (warp >= nrows) return;
    const float* r = src + (size_t)warp * DIM;
    __nv_bfloat16* d = dst + (size_t)warp * DIM;
    float s = 0.f;
    #pragma unroll
    for (int i = 0; i < DIM / 32; i++) {
        float v = r[lane + i * 32];
        d[lane + i * 32] = __float2bfloat16(v);
        s = __fadd_rn(s, __fmul_rn(v, v));
    }
    #pragma unroll
    for (int o = 16; o > 0; o >>= 1)
        s = __fadd_rn(s, __shfl_xor_sync(0xffffffffu, s, o));
    if (lane == 0) norms[warp] = s;
}

// ===========================================================================
// bf16 mma.sync (f32 acc) distance GEMM + top-2 shortlist + exact fp32 refine
// CTA: 256 threads, 8 warps (4m x 2n), warp tile 32x64, CTA tile 128x128.
// A (64KB) resident; B streamed 3 x 16KB stages, race-free order
// (wait -> sync -> issue c+2 -> mma c). 112KB smem, 2 CTAs/SM = 16 warps.
// Approx metric drops per-row A term (ordering-invariant). Fused enc zeroing.
// ===========================================================================
__global__ __launch_bounds__(256, 2)
void gemm_mma_kernel(const float* __restrict__ x, const float* __restrict__ w,
                     float* __restrict__ out_enc) {
    extern __shared__ char smem[];
    const uint32_t sbase = smem_u32(smem);
    const int tid  = threadIdx.x;
    const int wid  = tid >> 5;
    const int lane = tid & 31;
    const int warp_m = wid & 3;       // 32-row slab (0..3)
    const int warp_n = wid >> 2;      // 64-col slab (0..1)
    const int row0 = blockIdx.x * M_TILE;

    const uint32_t A_OFF = 0;                    // 64KB: 4 blocks of 16KB (per k-chunk)
    const uint32_t B_OFF = A_BYTES;              // 48KB B stages

    // enc slice for this CTA: rows [row0, row0+128)
    float* enc_slice = out_enc + (size_t)row0 * KC;
    float4* encz = (float4*)(enc_slice + 2);     // 16B-aligned (base is 8-mod-16)
    const int N_F4 = (M_TILE * KC - 4) / 4;      // 131071

    // ldmatrix per-lane geometry (canonical x4 non-trans)
    const int a_row_l = (((lane >> 3) & 1) << 3) + (lane & 7);
    const int a_seg   = (lane >> 4) << 4;
    const int b_n_l   = ((lane >> 4) << 3) + (lane & 7);
    const int b_seg   = ((lane >> 3) & 1) << 4;

    float acc[2][8][4];
    #pragma unroll
    for (int mi = 0; mi < 2; mi++)
        #pragma unroll
        for (int ni = 0; ni < 8; ni++)
            #pragma unroll
            for (int q = 0; q < 4; q++) acc[mi][ni][q] = 0.f;

    // top-2 per local row (4 local rows per thread: mi x h), lex-sorted
    float cv[4][2];
    int   ci[4][2];
    #pragma unroll
    for (int lr = 0; lr < 4; lr++) {
        cv[lr][0] = cv[lr][1] = 3.4e38f;
        ci[lr][0] = ci[lr][1] = 0x7fffffff;
    }

    const __nv_bfloat16* xs = g_Xbf + (size_t)row0 * DIM;

    // ---- load resident A (4 blocks x 16KB), one commit group ----
    #pragma unroll
    for (int blk = 0; blk < 4; blk++) {
        const uint32_t Ab = sbase + A_OFF + blk * 16384;
        const __nv_bfloat16* ga = xs + blk * K_CH;
        #pragma unroll
        for (int i = 0; i < 4; i++) {
            int id = tid + i * 256;
            int r = id >> 3, k8 = id & 7;
            CP_ASYNC16(Ab + swz(r * 128 + k8 * 16), ga + (size_t)r * DIM + k8 * 8);
        }
    }
    CP_COMMIT();

    // ---- B chunk issue (128 rows x 128B = 1024 x 16B; 4 per thread) ----
    #define ISSUE_B(cc_) do {                                                 \
        const int s_  = (cc_) % 3;                                            \
        const int nt_ = (cc_) >> 2;                                           \
        const int kc_ = (cc_) & 3;                                            \
        const uint32_t Bb_ = sbase + B_OFF + s_ * STG_BYTES;                  \
        const __nv_bfloat16* gb_ = g_Wbf + (size_t)(nt_ * NT_COLS) * DIM + kc_ * K_CH; \
        _Pragma("unroll")                                                     \
        for (int i = 0; i < 4; i++) {                                         \
            int id = tid + i * 256;                                           \
            int r = id >> 3, k8 = id & 7;                                     \
            CP_ASYNC16(Bb_ + swz(r * 128 + k8 * 16), gb_ + (size_t)r * DIM + k8 * 8); \
        }                                                                     \
        CP_COMMIT();                                                          \
    } while (0)

    ISSUE_B(0);
    ISSUE_B(1);

    #pragma unroll 1
    for (int c = 0; c < N_CHUNKS; c++) {
        if (c + 1 < N_CHUNKS) asm volatile("cp.async.wait_group 1;" ::: "memory");
        else                  asm volatile("cp.async.wait_group 0;" ::: "memory");
        __syncthreads();
        if (c + 2 < N_CHUNKS) ISSUE_B(c + 2);

        // fused enc zeroing: 4 coalesced float4 stores per thread per chunk
        {
            const float4 z4 = make_float4(0.f, 0.f, 0.f, 0.f);
            const int base = c * 1024 + tid;
            #pragma unroll
            for (int j = 0; j < 4; j++) {
                int idx = base + j * 256;
                if (idx < N_F4) encz[idx] = z4;
            }
            if (c == 0 && tid == 0) {
                enc_slice[0] = 0.f; enc_slice[1] = 0.f;
                enc_slice[(size_t)M_TILE * KC - 2] = 0.f;
                enc_slice[(size_t)M_TILE * KC - 1] = 0.f;
            }
        }

        const uint32_t Ab = sbase + A_OFF + (c & 3) * 16384;
        const uint32_t Bb = sbase + B_OFF + (c % 3) * STG_BYTES;

        #pragma unroll
        for (int k16 = 0; k16 < 4; k16++) {
            const int kb = k16 * 32;
            uint32_t af[2][4];
            #pragma unroll
            for (int mi = 0; mi < 2; mi++)
                ldsm4(af[mi], Ab + swz((warp_m * 32 + mi * 16 + a_row_l) * 128
                                       + kb + a_seg));
            uint32_t bf[4][4];
            #pragma unroll
            for (int p = 0; p < 4; p++)
                ldsm4(bf[p], Bb + swz((warp_n * 64 + p * 16 + b_n_l) * 128
                                      + kb + b_seg));
            #pragma unroll
            for (int mi = 0; mi < 2; mi++)
                #pragma unroll
                for (int ni = 0; ni < 8; ni++)
                    mma_bf16(acc[mi][ni], af[mi],
                             bf[ni >> 1][(ni & 1) * 2], bf[ni >> 1][(ni & 1) * 2 + 1]);
        }

        if ((c & 3) == 3) {
            // N-tile finished: approx v = B[col] - 2*d (A-term dropped), top-2
            const int nt = c >> 2;
            const int colbase = nt * NT_COLS + warp_n * 64;
            #pragma unroll
            for (int mi = 0; mi < 2; mi++)
                #pragma unroll
                for (int h = 0; h < 2; h++) {
                    const int lr = mi * 2 + h;
                    #pragma unroll
                    for (int ni = 0; ni < 8; ni++)
                        #pragma unroll
                        for (int cc = 0; cc < 2; cc++) {
                            const int col = colbase + ni * 8 + 2 * (lane & 3) + cc;
                            float d = acc[mi][ni][h * 2 + cc];
                            float v = __fsub_rn(g_B[col], __fmul_rn(2.0f, d));
                            if (lex_less(v, col, cv[lr][1], ci[lr][1])) {
                                if (lex_less(v, col, cv[lr][0], ci[lr][0])) {
                                    cv[lr][1] = cv[lr][0]; ci[lr][1] = ci[lr][0];
                                    cv[lr][0] = v;         ci[lr][0] = col;
                                } else {
                                    cv[lr][1] = v;         ci[lr][1] = col;
                                }
                            }
                            acc[mi][ni][h * 2 + cc] = 0.f;
                        }
                }
        }
    }

    // gather shortlist to smem (reuse A region): 128 rows x 16 entries
    __syncthreads();
    float* redv = (float*)smem;                    // 8KB
    int*   redi = (int*)(smem + 128 * 16 * 4);     // 8KB
    #pragma unroll
    for (int lr = 0; lr < 4; lr++) {
        int mi = lr >> 1, h = lr & 1;
        const int row = warp_m * 32 + mi * 16 + h * 8 + (lane >> 2);
        const int slot = (warp_n * 4 + (lane & 3)) * 2;
        #pragma unroll
        for (int j = 0; j < 2; j++) {
            redv[row * 16 + slot + j] = cv[lr][j];
            redi[row * 16 + slot + j] = ci[lr][j];
        }
    }
    __syncthreads();

    // exact fp32 refine: one thread per row (sequential fmaf order = R1-proven)
    if (tid < M_TILE) {
        const int row = row0 + tid;
        float gmin = 3.4e38f;
        #pragma unroll
        for (int j = 0; j < 16; j++)
            gmin = fminf(gmin, redv[tid * 16 + j]);
        const float thresh = gmin + EPS;
        const float Ar = g_A[row];
        const float* xr = x + (size_t)row * DIM;

        float bestv = 3.4e38f;
        int   besti = 0x7fffffff;
        for (int j = 0; j < 16; j++) {
            float va = redv[tid * 16 + j];
            int   col = redi[tid * 16 + j];
            if (va > thresh || col == 0x7fffffff) continue;
            const float* wr = w + (size_t)col * DIM;
            float dot = 0.f;
            #pragma unroll 8
            for (int k = 0; k < DIM; k++)
                dot = fmaf(xr[k], __ldg(wr + k), dot);
            float u = __fadd_rn(Ar, g_B[col]);
            float ve = __fsub_rn(u, __fmul_rn(2.0f, dot));
            if (lex_less(ve, col, bestv, besti)) { bestv = ve; besti = col; }
        }
        g_argmin[row] = besti;
    }
}

// ===========================================================================
// epilogue + finalize
// ===========================================================================
__global__ __launch_bounds__(256)
void epilogue_kernel(const float* __restrict__ x, const float* __restrict__ w,
                     float* __restrict__ out_qst, float* __restrict__ out_enc) {
    __shared__ double sred[256];
    const int tid = threadIdx.x;
    const int rowLocal = tid >> 2;
    const int sub = tid & 3;
    const int row = blockIdx.x * 64 + rowLocal;
    const int idx = g_argmin[row];

    const float* wr = w + (size_t)idx * DIM;
    const float* xr = x + (size_t)row * DIM;
    float* qr = out_qst + (size_t)row * DIM;

    double ls = 0.0;
    #pragma unroll 8
    for (int u = 0; u < DIM / 4; u++) {
        int e = u * 4 + sub;
        float wv = wr[e];
        float xv = xr[e];
        float dlt = __fsub_rn(wv, xv);
        qr[e] = __fadd_rn(xv, dlt);
        float t = __fmul_rn(dlt, dlt);
        ls += (double)t;
    }
    if (sub == 0) {
        out_enc[(size_t)row * KC + idx] = 1.0f;
        atomicAdd(&g_counts[idx], 1);
    }
    sred[tid] = ls;
    __syncthreads();
    #pragma unroll
    for (int s = 128; s > 0; s >>= 1) {
        if (tid < s) sred[tid] += sred[tid + s];
        __syncthreads();
    }
    if (tid == 0) g_partial[blockIdx.x] = sred[0];
}

__global__ __launch_bounds__(256)
void finalize_kernel(float* __restrict__ out_loss, float* __restrict__ out_perp) {
    __shared__ double sred[256];
    const int tid = threadIdx.x;

    double s = g_partial[tid] + g_partial[tid + 256];
    sred[tid] = s;
    __syncthreads();
    #pragma unroll
    for (int st = 128; st > 0; st >>= 1) {
        if (tid < st) sred[tid] += sred[tid + st];
        __syncthreads();
    }
    if (tid == 0) {
        double total = sred[0];
        float m = (float)(total / (double)((long long)N_IN * DIM));
        *out_loss = __fadd_rn(m, __fmul_rn(0.25f, m));
    }
    __syncthreads();

    double ps = 0.0;
    #pragma unroll
    for (int i = 0; i < KC / 256; i++) {
        int k = tid + i * 256;
        float p = (float)g_counts[k] * (1.0f / (float)N_IN);
        float term = p * logf(__fadd_rn(p, 1e-10f));
        ps += (double)term;
    }
    sred[tid] = ps;
    __syncthreads();
    #pragma unroll
    for (int st = 128; st > 0; st >>= 1) {
        if (tid < st) sred[tid] += sred[tid + st];
        __syncthreads();
    }
    if (tid == 0) *out_perp = expf((float)(-sred[0]));
}

// ===========================================================================
extern "C" void kernel_launch(void* const* d_in, const int* in_sizes, int n_in,
                              void* d_out, int out_size) {
    const float* x = (const float*)d_in[0];
    const float* w = (const float*)d_in[1];
    if (n_in >= 2 && in_sizes[0] == KC * DIM && in_sizes[1] == N_IN * DIM) {
        x = (const float*)d_in[1];
        w = (const float*)d_in[0];
    }

    float* out = (float*)d_out;
    float* out_loss = out;
    float* out_qst  = out + 1;
    float* out_perp = out + 1 + (size_t)N_IN * DIM;
    float* out_enc  = out + 2 + (size_t)N_IN * DIM;

    __nv_bfloat16* xbf = nullptr; __nv_bfloat16* wbf = nullptr;
    float* ga = nullptr; float* gb = nullptr;
    cudaGetSymbolAddress((void**)&xbf, g_Xbf);
    cudaGetSymbolAddress((void**)&wbf, g_Wbf);
    cudaGetSymbolAddress((void**)&ga, g_A);
    cudaGetSymbolAddress((void**)&gb, g_B);

    const int SMEM_BYTES = A_BYTES + STAGES * STG_BYTES;   // 112KB
    cudaFuncSetAttribute(gemm_mma_kernel, cudaFuncAttributeMaxDynamicSharedMemorySize, SMEM_BYTES);

    init_kernel<<<(KC + 255) / 256, 256>>>();
    prep_kernel<<<N_IN / 8, 256>>>(x, xbf, ga, N_IN);
    prep_kernel<<<KC / 8, 256>>>(w, wbf, gb, KC);

    gemm_mma_kernel<<<N_IN / M_TILE, 256, SMEM_BYTES>>>(x, w, out_enc);

    epilogue_kernel<<<N_IN / 64, 256>>>(x, w, out_qst, out_enc);
    finalize_kernel<<<1, 256>>>(out_loss, out_perp);
}